// round 7
// baseline (speedup 1.0000x reference)
#include <cuda_runtime.h>
#include <cuda_bf16.h>
#include <cstdint>
#include <math.h>

#define BATCH 8
#define SEQ 1024
#define NDIM 768
#define HEADS 12
#define DHEAD 64
#define INNER 768
#define QKV_COLS 2304
#define ROWS_TOTAL (BATCH * SEQ)   // 8192

// ---------------------------------------------------------------------------
// Device scratch (no cudaMalloc allowed)
// ---------------------------------------------------------------------------
__device__ float g_qkv[ROWS_TOTAL * QKV_COLS];   // fp32 (tf32-rounded)

__device__ __nv_bfloat16 g_xhi[ROWS_TOTAL * NDIM];
__device__ __nv_bfloat16 g_xlo[ROWS_TOTAL * NDIM];
__device__ __nv_bfloat16 g_whi[QKV_COLS * NDIM];
__device__ __nv_bfloat16 g_wlo[QKV_COLS * NDIM];
__device__ __nv_bfloat16 g_ahi[ROWS_TOTAL * NDIM];
__device__ __nv_bfloat16 g_alo[ROWS_TOTAL * NDIM];
__device__ __nv_bfloat16 g_vhi[NDIM * NDIM];
__device__ __nv_bfloat16 g_vlo[NDIM * NDIM];

// ---------------------------------------------------------------------------
// Helpers (baseline PTX, valid on compute_103)
// ---------------------------------------------------------------------------
__device__ __forceinline__ uint32_t smem_u32(const void* p) {
    uint32_t a;
    asm("{ .reg .u64 t; cvta.to.shared.u64 t, %1; cvt.u32.u64 %0, t; }"
        : "=r"(a) : "l"(p));
    return a;
}

__device__ __forceinline__ uint32_t f2tf32(float f) {
    uint32_t u;
    asm("cvt.rna.tf32.f32 %0, %1;" : "=r"(u) : "f"(f));
    return u;
}

__device__ __forceinline__ void mma_bf16(float* c, const uint32_t* a,
                                         uint32_t b0, uint32_t b1) {
    asm volatile(
        "mma.sync.aligned.m16n8k16.row.col.f32.bf16.bf16.f32 "
        "{%0,%1,%2,%3},{%4,%5,%6,%7},{%8,%9},{%0,%1,%2,%3};"
        : "+f"(c[0]), "+f"(c[1]), "+f"(c[2]), "+f"(c[3])
        : "r"(a[0]), "r"(a[1]), "r"(a[2]), "r"(a[3]), "r"(b0), "r"(b1));
}

__device__ __forceinline__ void mma_tf32(float* c, const uint32_t* a,
                                         uint32_t b0, uint32_t b1) {
    asm volatile(
        "mma.sync.aligned.m16n8k8.row.col.f32.tf32.tf32.f32 "
        "{%0,%1,%2,%3},{%4,%5,%6,%7},{%8,%9},{%0,%1,%2,%3};"
        : "+f"(c[0]), "+f"(c[1]), "+f"(c[2]), "+f"(c[3])
        : "r"(a[0]), "r"(a[1]), "r"(a[2]), "r"(a[3]), "r"(b0), "r"(b1));
}

__device__ __forceinline__ void ldm4(uint32_t* a, uint32_t addr) {
    asm volatile("ldmatrix.sync.aligned.m8n8.x4.shared.b16 {%0,%1,%2,%3}, [%4];"
                 : "=r"(a[0]), "=r"(a[1]), "=r"(a[2]), "=r"(a[3]) : "r"(addr));
}

__device__ __forceinline__ void cp_async16(uint32_t dst, const void* src) {
    asm volatile("cp.async.cg.shared.global [%0], [%1], 16;" ::"r"(dst),
                 "l"(src));
}
#define CP_COMMIT() asm volatile("cp.async.commit_group;" ::: "memory")
#define CP_WAIT0() asm volatile("cp.async.wait_group 0;" ::: "memory")
#define CP_WAIT1() asm volatile("cp.async.wait_group 1;" ::: "memory")

// ---------------------------------------------------------------------------
// Conversion kernel: fp32 -> bf16 hi + bf16 lo
// ---------------------------------------------------------------------------
__global__ void __launch_bounds__(256) cvt_hilo(const float* __restrict__ src,
                                                __nv_bfloat16* __restrict__ hi,
                                                __nv_bfloat16* __restrict__ lo,
                                                int n4) {
    int i = blockIdx.x * blockDim.x + threadIdx.x;
    int stride = gridDim.x * blockDim.x;
    for (; i < n4; i += stride) {
        float4 v = ((const float4*)src)[i];
        __nv_bfloat16 h0 = __float2bfloat16(v.x);
        __nv_bfloat16 h1 = __float2bfloat16(v.y);
        __nv_bfloat16 h2 = __float2bfloat16(v.z);
        __nv_bfloat16 h3 = __float2bfloat16(v.w);
        __nv_bfloat16 l0 = __float2bfloat16(v.x - __bfloat162float(h0));
        __nv_bfloat16 l1 = __float2bfloat16(v.y - __bfloat162float(h1));
        __nv_bfloat16 l2 = __float2bfloat16(v.z - __bfloat162float(h2));
        __nv_bfloat16 l3 = __float2bfloat16(v.w - __bfloat162float(h3));
        __nv_bfloat162* hp = (__nv_bfloat162*)hi;
        __nv_bfloat162* lp = (__nv_bfloat162*)lo;
        __nv_bfloat162 a, b;
        a.x = h0; a.y = h1; b.x = h2; b.y = h3;
        hp[2 * i] = a; hp[2 * i + 1] = b;
        a.x = l0; a.y = l1; b.x = l2; b.y = l3;
        lp[2 * i] = a; lp[2 * i + 1] = b;
    }
}

// ---------------------------------------------------------------------------
// bf16x3 GEMM via mma.sync (NT): C = A @ B^T (+bias) (optional tf32 rounding)
// 128x128 tile, BK=32, 256 threads (8 warps, 32x64 each), cp.async dbl-buffer.
// Mainloop: A frags loaded once per k16 chunk; B tiles processed in pairs so
// accumulator RAW chains are >= 8 mmas apart and ldm4 results have long
// load->use distance.
// ---------------------------------------------------------------------------
#define GK 32
#define TILE_B 10240        // 128 rows * 80 bytes
#define BUF_B (4 * TILE_B)  // Ahi | Alo | Bhi | Blo
#define GEMM_SMEM (2 * BUF_B)

template <bool HAS_BIAS, bool ROUND_TF32>
__global__ void __launch_bounds__(256) gemm_bf16x3(
    const __nv_bfloat16* __restrict__ Ahi, const __nv_bfloat16* __restrict__ Alo,
    const __nv_bfloat16* __restrict__ Bhi, const __nv_bfloat16* __restrict__ Blo,
    const float* __restrict__ bias, float* __restrict__ C, int M, int N, int K) {
    extern __shared__ char gsm[];
    const uint32_t sbase = smem_u32(gsm);

    const int tid = threadIdx.x;
    const int w = tid >> 5, l = tid & 31;
    const int g = l >> 2, t4 = l & 3;
    const int bm = blockIdx.y * 128, bn = blockIdx.x * 128;
    const int mrow0 = (w & 3) * 32, ncol0 = (w >> 2) * 64;

    const __nv_bfloat16* tsrc[4] = {Ahi, Alo, Bhi, Blo};

    float acc[2][8][4];
#pragma unroll
    for (int mi = 0; mi < 2; mi++)
#pragma unroll
        for (int ni = 0; ni < 8; ni++)
#pragma unroll
            for (int q = 0; q < 4; q++) acc[mi][ni][q] = 0.f;

    const int arow = (l & 7) + ((l >> 3) & 1) * 8;
    const int acolb = ((l >> 4) & 1) * 16;

    auto load_chunk = [&](int c) {
        const int k0 = c * GK;
        const uint32_t db = sbase + (uint32_t)(c & 1) * BUF_B;
#pragma unroll
        for (int t = 0; t < 4; t++) {
            const __nv_bfloat16* src = tsrc[t];
            const int rb = (t < 2) ? bm : bn;
#pragma unroll
            for (int i = 0; i < 2; i++) {
                int u = tid + i * 256;
                int row = u >> 2, seg = u & 3;
                const void* gp = src + (size_t)(rb + row) * K + k0 + seg * 8;
                uint32_t sp = db + (uint32_t)(t * TILE_B + row * 80 + seg * 16);
                cp_async16(sp, gp);
            }
        }
        CP_COMMIT();
    };

    const int nchunk = K / GK;
    load_chunk(0);

    for (int c = 0; c < nchunk; c++) {
        CP_WAIT0();
        __syncthreads();
        if (c + 1 < nchunk) load_chunk(c + 1);

        const uint32_t bb = sbase + (uint32_t)(c & 1) * BUF_B;
#pragma unroll
        for (int kc = 0; kc < 2; kc++) {
            const uint32_t kcoff = (uint32_t)(kc * 32 + acolb);
            uint32_t ahi_[2][4], alo_[2][4];
            ldm4(ahi_[0], bb + (uint32_t)((mrow0 + arow) * 80) + kcoff);
            ldm4(ahi_[1], bb + (uint32_t)((mrow0 + 16 + arow) * 80) + kcoff);
            ldm4(alo_[0], bb + TILE_B + (uint32_t)((mrow0 + arow) * 80) + kcoff);
            ldm4(alo_[1],
                 bb + TILE_B + (uint32_t)((mrow0 + 16 + arow) * 80) + kcoff);

#pragma unroll
            for (int nio = 0; nio < 2; nio++) {
                // B frags for two adjacent n16 tiles (hi and lo each)
                uint32_t bh[2][4], bl[2][4];
#pragma unroll
                for (int j = 0; j < 2; j++) {
                    const uint32_t boff =
                        (uint32_t)((ncol0 + (nio * 2 + j) * 16 + arow) * 80) +
                        kcoff;
                    ldm4(bh[j], bb + 2 * TILE_B + boff);
                    ldm4(bl[j], bb + 3 * TILE_B + boff);
                }
                const int n0 = nio * 4;
                // pass 1: Ahi x Bhi  (8 mma, 8 distinct accumulators)
#pragma unroll
                for (int j = 0; j < 2; j++) {
                    mma_bf16(acc[0][n0 + 2 * j], ahi_[0], bh[j][0], bh[j][2]);
                    mma_bf16(acc[1][n0 + 2 * j], ahi_[1], bh[j][0], bh[j][2]);
                    mma_bf16(acc[0][n0 + 2 * j + 1], ahi_[0], bh[j][1], bh[j][3]);
                    mma_bf16(acc[1][n0 + 2 * j + 1], ahi_[1], bh[j][1], bh[j][3]);
                }
                // pass 2: Ahi x Blo
#pragma unroll
                for (int j = 0; j < 2; j++) {
                    mma_bf16(acc[0][n0 + 2 * j], ahi_[0], bl[j][0], bl[j][2]);
                    mma_bf16(acc[1][n0 + 2 * j], ahi_[1], bl[j][0], bl[j][2]);
                    mma_bf16(acc[0][n0 + 2 * j + 1], ahi_[0], bl[j][1], bl[j][3]);
                    mma_bf16(acc[1][n0 + 2 * j + 1], ahi_[1], bl[j][1], bl[j][3]);
                }
                // pass 3: Alo x Bhi
#pragma unroll
                for (int j = 0; j < 2; j++) {
                    mma_bf16(acc[0][n0 + 2 * j], alo_[0], bh[j][0], bh[j][2]);
                    mma_bf16(acc[1][n0 + 2 * j], alo_[1], bh[j][0], bh[j][2]);
                    mma_bf16(acc[0][n0 + 2 * j + 1], alo_[0], bh[j][1], bh[j][3]);
                    mma_bf16(acc[1][n0 + 2 * j + 1], alo_[1], bh[j][1], bh[j][3]);
                }
            }
        }
    }

#pragma unroll
    for (int mi = 0; mi < 2; mi++) {
        const int r0 = bm + mrow0 + mi * 16 + g;
#pragma unroll
        for (int ni = 0; ni < 8; ni++) {
            const int col = bn + ncol0 + ni * 8 + 2 * t4;
            float b0v = 0.f, b1v = 0.f;
            if (HAS_BIAS) { b0v = bias[col]; b1v = bias[col + 1]; }
            float vals[4];
            vals[0] = acc[mi][ni][0] + b0v; vals[1] = acc[mi][ni][1] + b1v;
            vals[2] = acc[mi][ni][2] + b0v; vals[3] = acc[mi][ni][3] + b1v;
            if (ROUND_TF32) {
#pragma unroll
                for (int q = 0; q < 4; q++)
                    vals[q] = __uint_as_float(f2tf32(vals[q]));
            }
            float2 v0, v1;
            v0.x = vals[0]; v0.y = vals[1];
            v1.x = vals[2]; v1.y = vals[3];
            *(float2*)(C + (size_t)r0 * N + col) = v0;
            *(float2*)(C + (size_t)(r0 + 8) * N + col) = v1;
        }
    }
}

// ---------------------------------------------------------------------------
// Fused shuffled-Q flash attention (tf32 mma.sync).
// 256 threads (8 warps), 128 q-rows/block, KV tiles of 64.
// Ring of 3 KV buffers -> a single __syncthreads per KV tile.
// Q staged in buffer 2 (first overwritten by tile 2, after Q frags are in regs).
// ---------------------------------------------------------------------------
#define KSTR 68
#define VSTR 72
#define QSTR 70
#define KVBUF 8960                    // words: 64*68 + 64*72
#define VOFF 4352                     // words: 64*68
#define ATT_SMEM (3 * KVBUF * 4)      // 107520 bytes

__global__ void __launch_bounds__(256, 2) attn_kernel(
    const float* __restrict__ qkv, const int* __restrict__ perms,
    __nv_bfloat16* __restrict__ out_hi, __nv_bfloat16* __restrict__ out_lo) {
    extern __shared__ uint32_t sms[];
    const uint32_t sbase = smem_u32(sms);

    const int bh = blockIdx.y;
    const int b = bh / HEADS;
    const int h = bh % HEADS;
    const int q0 = blockIdx.x * 128;

    const int tid = threadIdx.x;
    const int w = tid >> 5, l = tid & 31;
    const int g = l >> 2, t4 = l & 3;
    const int qr0 = w * 16;

    const float* qkv_b = qkv + (size_t)b * SEQ * QKV_COLS;
    const int hoff = h * DHEAD;

    const int cp_row = tid >> 4;
    const int cp_seg = (tid & 15) * 4;

    auto issue_kv = [&](int t, int bsel) {
        const int kv0 = t * 64;
        const float* kb = qkv_b + (size_t)kv0 * QKV_COLS + hoff + INNER + cp_seg;
        const float* vb = kb + INNER;
        const uint32_t kd = sbase + (uint32_t)(bsel * KVBUF) * 4;
#pragma unroll
        for (int i = 0; i < 4; i++) {
            const int row = cp_row + i * 16;
            cp_async16(kd + (uint32_t)(row * KSTR + cp_seg) * 4,
                       kb + (size_t)row * QKV_COLS);
        }
#pragma unroll
        for (int i = 0; i < 4; i++) {
            const int row = cp_row + i * 16;
            cp_async16(kd + (uint32_t)(VOFF + row * VSTR + cp_seg) * 4,
                       vb + (size_t)row * QKV_COLS);
        }
        CP_COMMIT();
    };

    issue_kv(0, 0);

    // Stage Q (permuted, scaled, tf32) in buffer 2.
    const int* ph = perms + (size_t)h * (SEQ * DHEAD) + q0 * DHEAD;
#pragma unroll 4
    for (int it = 0; it < 32; it++) {
        int f = it * 256 + tid;
        int p = ph[f];
        int nn = p >> 6, dd = p & 63;
        int i = f >> 6, j = f & 63;
        sms[2 * KVBUF + i * QSTR + j] =
            f2tf32(qkv_b[(size_t)nn * QKV_COLS + hoff + dd] * 0.125f);
    }
    __syncthreads();

    uint32_t qf[8][4];
#pragma unroll
    for (int kc = 0; kc < 8; kc++) {
        qf[kc][0] = sms[2 * KVBUF + (qr0 + g) * QSTR + kc * 8 + t4];
        qf[kc][1] = sms[2 * KVBUF + (qr0 + g + 8) * QSTR + kc * 8 + t4];
        qf[kc][2] = sms[2 * KVBUF + (qr0 + g) * QSTR + kc * 8 + t4 + 4];
        qf[kc][3] = sms[2 * KVBUF + (qr0 + g + 8) * QSTR + kc * 8 + t4 + 4];
    }
    __syncthreads();   // all warps done reading buf2 before tile-2 overwrite

    float m0 = -1e30f, m1 = -1e30f, l0 = 0.f, l1 = 0.f;
    float O[8][4];
#pragma unroll
    for (int dt = 0; dt < 8; dt++)
#pragma unroll
        for (int q = 0; q < 4; q++) O[dt][q] = 0.f;

    const int srcA = (l & 28) | (t4 >> 1);
    const int srcB = srcA | 2;
    const bool lo_lane = (t4 & 1) != 0;

    int bsel = 0, bnext = 1;
    for (int t = 0; t < 16; t++) {
        if (t < 15) {
            issue_kv(t + 1, bnext);
            CP_WAIT1();
        } else {
            CP_WAIT0();
        }
        __syncthreads();   // tile t visible; max warp skew = 1 iter (ring of 3)

        const uint32_t kw = (uint32_t)bsel * KVBUF;
        const uint32_t vw = kw + VOFF;
        bsel = bnext;
        bnext = (bnext == 2) ? 0 : bnext + 1;

        float S[8][4];
#pragma unroll
        for (int nt = 0; nt < 8; nt++)
#pragma unroll
            for (int q = 0; q < 4; q++) S[nt][q] = 0.f;
#pragma unroll
        for (int kc = 0; kc < 8; kc++) {
#pragma unroll
            for (int nt = 0; nt < 8; nt++) {
                uint32_t b0 = sms[kw + (nt * 8 + g) * KSTR + kc * 8 + t4];
                uint32_t b1 = sms[kw + (nt * 8 + g) * KSTR + kc * 8 + t4 + 4];
                mma_tf32(S[nt], qf[kc], b0, b1);
            }
        }

        float mx0 = -1e30f, mx1 = -1e30f;
#pragma unroll
        for (int nt = 0; nt < 8; nt++) {
            mx0 = fmaxf(mx0, fmaxf(S[nt][0], S[nt][1]));
            mx1 = fmaxf(mx1, fmaxf(S[nt][2], S[nt][3]));
        }
        mx0 = fmaxf(mx0, __shfl_xor_sync(0xffffffffu, mx0, 1));
        mx0 = fmaxf(mx0, __shfl_xor_sync(0xffffffffu, mx0, 2));
        mx1 = fmaxf(mx1, __shfl_xor_sync(0xffffffffu, mx1, 1));
        mx1 = fmaxf(mx1, __shfl_xor_sync(0xffffffffu, mx1, 2));

        const float mn0 = fmaxf(m0, mx0);
        const float mn1 = fmaxf(m1, mx1);
        const float al0 = __expf(m0 - mn0);
        const float al1 = __expf(m1 - mn1);
        float sum0 = 0.f, sum1 = 0.f;
#pragma unroll
        for (int nt = 0; nt < 8; nt++) {
            S[nt][0] = __expf(S[nt][0] - mn0);
            S[nt][1] = __expf(S[nt][1] - mn0);
            S[nt][2] = __expf(S[nt][2] - mn1);
            S[nt][3] = __expf(S[nt][3] - mn1);
            sum0 += S[nt][0] + S[nt][1];
            sum1 += S[nt][2] + S[nt][3];
        }
        sum0 += __shfl_xor_sync(0xffffffffu, sum0, 1);
        sum0 += __shfl_xor_sync(0xffffffffu, sum0, 2);
        sum1 += __shfl_xor_sync(0xffffffffu, sum1, 1);
        sum1 += __shfl_xor_sync(0xffffffffu, sum1, 2);
        l0 = l0 * al0 + sum0;
        l1 = l1 * al1 + sum1;
        m0 = mn0; m1 = mn1;
#pragma unroll
        for (int dt = 0; dt < 8; dt++) {
            O[dt][0] *= al0; O[dt][1] *= al0;
            O[dt][2] *= al1; O[dt][3] *= al1;
        }

#pragma unroll
        for (int kc = 0; kc < 8; kc++) {
            uint32_t p0 = f2tf32(S[kc][0]);
            uint32_t p1 = f2tf32(S[kc][1]);
            uint32_t p2 = f2tf32(S[kc][2]);
            uint32_t p3 = f2tf32(S[kc][3]);
            uint32_t v00 = __shfl_sync(0xffffffffu, p0, srcA);
            uint32_t v01 = __shfl_sync(0xffffffffu, p1, srcA);
            uint32_t v10 = __shfl_sync(0xffffffffu, p2, srcA);
            uint32_t v11 = __shfl_sync(0xffffffffu, p3, srcA);
            uint32_t w00 = __shfl_sync(0xffffffffu, p0, srcB);
            uint32_t w01 = __shfl_sync(0xffffffffu, p1, srcB);
            uint32_t w10 = __shfl_sync(0xffffffffu, p2, srcB);
            uint32_t w11 = __shfl_sync(0xffffffffu, p3, srcB);
            uint32_t a[4];
            a[0] = lo_lane ? v01 : v00;
            a[1] = lo_lane ? v11 : v10;
            a[2] = lo_lane ? w01 : w00;
            a[3] = lo_lane ? w11 : w10;
#pragma unroll
            for (int dt = 0; dt < 8; dt++) {
                uint32_t b0 = sms[vw + (kc * 8 + t4) * VSTR + dt * 8 + g];
                uint32_t b1 = sms[vw + (kc * 8 + t4 + 4) * VSTR + dt * 8 + g];
                mma_tf32(O[dt], a, b0, b1);
            }
        }
        // no bottom sync: ring-of-3 guarantees the buffer written next iter
        // is not the one any (≤1-iter-behind) warp is still reading.
    }

    // Epilogue: normalize and write bf16 hi/lo pairs.
    const float inv0 = 1.0f / l0;
    const float inv1 = 1.0f / l1;
    const size_t r0off = ((size_t)b * SEQ + q0 + qr0 + g) * NDIM + hoff;
    const size_t r1off = r0off + (size_t)8 * NDIM;
#pragma unroll
    for (int dt = 0; dt < 8; dt++) {
        float f00 = O[dt][0] * inv0, f01 = O[dt][1] * inv0;
        float f10 = O[dt][2] * inv1, f11 = O[dt][3] * inv1;
        __nv_bfloat162 h0, h1, e0, e1;
        h0.x = __float2bfloat16(f00); h0.y = __float2bfloat16(f01);
        h1.x = __float2bfloat16(f10); h1.y = __float2bfloat16(f11);
        e0.x = __float2bfloat16(f00 - __bfloat162float(h0.x));
        e0.y = __float2bfloat16(f01 - __bfloat162float(h0.y));
        e1.x = __float2bfloat16(f10 - __bfloat162float(h1.x));
        e1.y = __float2bfloat16(f11 - __bfloat162float(h1.y));
        const int c = dt * 8 + 2 * t4;
        *(__nv_bfloat162*)(out_hi + r0off + c) = h0;
        *(__nv_bfloat162*)(out_lo + r0off + c) = e0;
        *(__nv_bfloat162*)(out_hi + r1off + c) = h1;
        *(__nv_bfloat162*)(out_lo + r1off + c) = e1;
    }
}

// ---------------------------------------------------------------------------
extern "C" void kernel_launch(void* const* d_in, const int* in_sizes, int n_in,
                              void* d_out, int out_size) {
    const float* x     = (const float*)d_in[0];
    const float* w_qkv = (const float*)d_in[1];
    const float* w_out = (const float*)d_in[2];
    const float* b_out = (const float*)d_in[3];
    const int*   perms = (const int*)d_in[4];
    float* out = (float*)d_out;

    float* qkv = nullptr;
    cudaGetSymbolAddress((void**)&qkv, g_qkv);
    __nv_bfloat16 *xhi, *xlo, *whi, *wlo, *ahi, *alo, *vhi, *vlo;
    cudaGetSymbolAddress((void**)&xhi, g_xhi);
    cudaGetSymbolAddress((void**)&xlo, g_xlo);
    cudaGetSymbolAddress((void**)&whi, g_whi);
    cudaGetSymbolAddress((void**)&wlo, g_wlo);
    cudaGetSymbolAddress((void**)&ahi, g_ahi);
    cudaGetSymbolAddress((void**)&alo, g_alo);
    cudaGetSymbolAddress((void**)&vhi, g_vhi);
    cudaGetSymbolAddress((void**)&vlo, g_vlo);

    cudaFuncSetAttribute(attn_kernel, cudaFuncAttributeMaxDynamicSharedMemorySize,
                         ATT_SMEM);
    cudaFuncSetAttribute((const void*)gemm_bf16x3<false, true>,
                         cudaFuncAttributeMaxDynamicSharedMemorySize, GEMM_SMEM);
    cudaFuncSetAttribute((const void*)gemm_bf16x3<true, false>,
                         cudaFuncAttributeMaxDynamicSharedMemorySize, GEMM_SMEM);

    // 1) split x / w_qkv / w_out into bf16 hi/lo
    {
        int n4 = ROWS_TOTAL * NDIM / 4;
        cvt_hilo<<<2048, 256>>>(x, xhi, xlo, n4);
        int m4 = QKV_COLS * NDIM / 4;
        cvt_hilo<<<1024, 256>>>(w_qkv, whi, wlo, m4);
        int v4 = NDIM * NDIM / 4;
        cvt_hilo<<<576, 256>>>(w_out, vhi, vlo, v4);
    }
    // 2) qkv = x @ w_qkv^T  (bf16x3 mma.sync, epilogue rounds to tf32)
    {
        dim3 grid(QKV_COLS / 128, ROWS_TOTAL / 128);  // (18, 64)
        gemm_bf16x3<false, true><<<grid, 256, GEMM_SMEM>>>(
            xhi, xlo, whi, wlo, nullptr, qkv, ROWS_TOTAL, QKV_COLS, NDIM);
    }
    // 3) fused shuffled-Q attention (tf32 mma.sync) -> bf16 hi/lo
    {
        dim3 grid(SEQ / 128, BATCH * HEADS);  // (8, 96)
        attn_kernel<<<grid, 256, ATT_SMEM>>>(qkv, perms, ahi, alo);
    }
    // 4) out = att @ w_out^T + b_out  (bf16x3 mma.sync)
    {
        dim3 grid(NDIM / 128, ROWS_TOTAL / 128);  // (6, 64)
        gemm_bf16x3<true, false><<<grid, 256, GEMM_SMEM>>>(
            ahi, alo, vhi, vlo, b_out, out, ROWS_TOTAL, NDIM, NDIM);
    }
}

// round 8
// speedup vs baseline: 1.0788x; 1.0788x over previous
#include <cuda_runtime.h>
#include <cuda_bf16.h>
#include <cstdint>
#include <math.h>

#define BATCH 8
#define SEQ 1024
#define NDIM 768
#define HEADS 12
#define DHEAD 64
#define INNER 768
#define QKV_COLS 2304
#define ROWS_TOTAL (BATCH * SEQ)   // 8192

// ---------------------------------------------------------------------------
// Device scratch (no cudaMalloc allowed)
// ---------------------------------------------------------------------------
__device__ float g_qkv[ROWS_TOTAL * QKV_COLS];   // fp32 (tf32-rounded)

__device__ __nv_bfloat16 g_xhi[ROWS_TOTAL * NDIM];
__device__ __nv_bfloat16 g_xlo[ROWS_TOTAL * NDIM];
__device__ __nv_bfloat16 g_whi[QKV_COLS * NDIM];
__device__ __nv_bfloat16 g_wlo[QKV_COLS * NDIM];
__device__ __nv_bfloat16 g_ahi[ROWS_TOTAL * NDIM];
__device__ __nv_bfloat16 g_alo[ROWS_TOTAL * NDIM];
__device__ __nv_bfloat16 g_vhi[NDIM * NDIM];
__device__ __nv_bfloat16 g_vlo[NDIM * NDIM];

// ---------------------------------------------------------------------------
// Helpers (baseline PTX, valid on compute_103)
// ---------------------------------------------------------------------------
__device__ __forceinline__ uint32_t smem_u32(const void* p) {
    uint32_t a;
    asm("{ .reg .u64 t; cvta.to.shared.u64 t, %1; cvt.u32.u64 %0, t; }"
        : "=r"(a) : "l"(p));
    return a;
}

__device__ __forceinline__ uint32_t f2tf32(float f) {
    uint32_t u;
    asm("cvt.rna.tf32.f32 %0, %1;" : "=r"(u) : "f"(f));
    return u;
}

__device__ __forceinline__ void mma_bf16(float* c, const uint32_t* a,
                                         uint32_t b0, uint32_t b1) {
    asm volatile(
        "mma.sync.aligned.m16n8k16.row.col.f32.bf16.bf16.f32 "
        "{%0,%1,%2,%3},{%4,%5,%6,%7},{%8,%9},{%0,%1,%2,%3};"
        : "+f"(c[0]), "+f"(c[1]), "+f"(c[2]), "+f"(c[3])
        : "r"(a[0]), "r"(a[1]), "r"(a[2]), "r"(a[3]), "r"(b0), "r"(b1));
}

__device__ __forceinline__ void mma_tf32(float* c, const uint32_t* a,
                                         uint32_t b0, uint32_t b1) {
    asm volatile(
        "mma.sync.aligned.m16n8k8.row.col.f32.tf32.tf32.f32 "
        "{%0,%1,%2,%3},{%4,%5,%6,%7},{%8,%9},{%0,%1,%2,%3};"
        : "+f"(c[0]), "+f"(c[1]), "+f"(c[2]), "+f"(c[3])
        : "r"(a[0]), "r"(a[1]), "r"(a[2]), "r"(a[3]), "r"(b0), "r"(b1));
}

__device__ __forceinline__ void ldm4(uint32_t* a, uint32_t addr) {
    asm volatile("ldmatrix.sync.aligned.m8n8.x4.shared.b16 {%0,%1,%2,%3}, [%4];"
                 : "=r"(a[0]), "=r"(a[1]), "=r"(a[2]), "=r"(a[3]) : "r"(addr));
}

__device__ __forceinline__ void cp_async16(uint32_t dst, const void* src) {
    asm volatile("cp.async.cg.shared.global [%0], [%1], 16;" ::"r"(dst),
                 "l"(src));
}
#define CP_COMMIT() asm volatile("cp.async.commit_group;" ::: "memory")
#define CP_WAIT0() asm volatile("cp.async.wait_group 0;" ::: "memory")
#define CP_WAIT1() asm volatile("cp.async.wait_group 1;" ::: "memory")

// d-interleave placement: P(8a+b) = 8a + ((b&3)*2 + (b>>2))
__device__ __forceinline__ int dplace(int j) {
    int b = j & 7;
    return (j & 0x38) | (((b & 3) << 1) | (b >> 2));
}

// ---------------------------------------------------------------------------
// Conversion kernels: fp32 -> bf16 hi + bf16 lo
// ---------------------------------------------------------------------------
__global__ void __launch_bounds__(256) cvt_hilo(const float* __restrict__ src,
                                                __nv_bfloat16* __restrict__ hi,
                                                __nv_bfloat16* __restrict__ lo,
                                                int n4) {
    int i = blockIdx.x * blockDim.x + threadIdx.x;
    int stride = gridDim.x * blockDim.x;
    for (; i < n4; i += stride) {
        float4 v = ((const float4*)src)[i];
        __nv_bfloat16 h0 = __float2bfloat16(v.x);
        __nv_bfloat16 h1 = __float2bfloat16(v.y);
        __nv_bfloat16 h2 = __float2bfloat16(v.z);
        __nv_bfloat16 h3 = __float2bfloat16(v.w);
        __nv_bfloat16 l0 = __float2bfloat16(v.x - __bfloat162float(h0));
        __nv_bfloat16 l1 = __float2bfloat16(v.y - __bfloat162float(h1));
        __nv_bfloat16 l2 = __float2bfloat16(v.z - __bfloat162float(h2));
        __nv_bfloat16 l3 = __float2bfloat16(v.w - __bfloat162float(h3));
        __nv_bfloat162* hp = (__nv_bfloat162*)hi;
        __nv_bfloat162* lp = (__nv_bfloat162*)lo;
        __nv_bfloat162 a, b;
        a.x = h0; a.y = h1; b.x = h2; b.y = h3;
        hp[2 * i] = a; hp[2 * i + 1] = b;
        a.x = l0; a.y = l1; b.x = l2; b.y = l3;
        lp[2 * i] = a; lp[2 * i + 1] = b;
    }
}

// w_qkv variant: rows in the K section [768,1536) are written to a
// d-interleaved destination row so gemm1's K output columns (and thus the
// attention K smem tiles, loaded via cp.async) are placement-interleaved.
__global__ void __launch_bounds__(256) cvt_hilo_wqkv(
    const float* __restrict__ src, __nv_bfloat16* __restrict__ hi,
    __nv_bfloat16* __restrict__ lo, int n4) {
    int i = blockIdx.x * blockDim.x + threadIdx.x;
    int stride = gridDim.x * blockDim.x;
    const int UPR = NDIM / 4;  // 192 float4 units per row
    for (; i < n4; i += stride) {
        float4 v = ((const float4*)src)[i];
        int row = i / UPR;
        int c4 = i - row * UPR;
        int drow = row;
        if (row >= INNER && row < 2 * INNER) {
            int d = (row - INNER) & 63;
            drow = (row & ~63) | dplace(d);
        }
        int di = drow * UPR + c4;
        __nv_bfloat16 h0 = __float2bfloat16(v.x);
        __nv_bfloat16 h1 = __float2bfloat16(v.y);
        __nv_bfloat16 h2 = __float2bfloat16(v.z);
        __nv_bfloat16 h3 = __float2bfloat16(v.w);
        __nv_bfloat16 l0 = __float2bfloat16(v.x - __bfloat162float(h0));
        __nv_bfloat16 l1 = __float2bfloat16(v.y - __bfloat162float(h1));
        __nv_bfloat16 l2 = __float2bfloat16(v.z - __bfloat162float(h2));
        __nv_bfloat16 l3 = __float2bfloat16(v.w - __bfloat162float(h3));
        __nv_bfloat162* hp = (__nv_bfloat162*)hi;
        __nv_bfloat162* lp = (__nv_bfloat162*)lo;
        __nv_bfloat162 a, b;
        a.x = h0; a.y = h1; b.x = h2; b.y = h3;
        hp[2 * di] = a; hp[2 * di + 1] = b;
        a.x = l0; a.y = l1; b.x = l2; b.y = l3;
        lp[2 * di] = a; lp[2 * di + 1] = b;
    }
}

// ---------------------------------------------------------------------------
// bf16x3 GEMM via mma.sync (NT): C = A @ B^T (+bias) (optional tf32 rounding)
// ---------------------------------------------------------------------------
#define GK 32
#define TILE_B 10240        // 128 rows * 80 bytes
#define BUF_B (4 * TILE_B)
#define GEMM_SMEM (2 * BUF_B)

template <bool HAS_BIAS, bool ROUND_TF32>
__global__ void __launch_bounds__(256) gemm_bf16x3(
    const __nv_bfloat16* __restrict__ Ahi, const __nv_bfloat16* __restrict__ Alo,
    const __nv_bfloat16* __restrict__ Bhi, const __nv_bfloat16* __restrict__ Blo,
    const float* __restrict__ bias, float* __restrict__ C, int M, int N, int K) {
    extern __shared__ char gsm[];
    const uint32_t sbase = smem_u32(gsm);

    const int tid = threadIdx.x;
    const int w = tid >> 5, l = tid & 31;
    const int g = l >> 2, t4 = l & 3;
    const int bm = blockIdx.y * 128, bn = blockIdx.x * 128;
    const int mrow0 = (w & 3) * 32, ncol0 = (w >> 2) * 64;

    const __nv_bfloat16* tsrc[4] = {Ahi, Alo, Bhi, Blo};

    float acc[2][8][4];
#pragma unroll
    for (int mi = 0; mi < 2; mi++)
#pragma unroll
        for (int ni = 0; ni < 8; ni++)
#pragma unroll
            for (int q = 0; q < 4; q++) acc[mi][ni][q] = 0.f;

    const int arow = (l & 7) + ((l >> 3) & 1) * 8;
    const int acolb = ((l >> 4) & 1) * 16;

    auto load_chunk = [&](int c) {
        const int k0 = c * GK;
        const uint32_t db = sbase + (uint32_t)(c & 1) * BUF_B;
#pragma unroll
        for (int t = 0; t < 4; t++) {
            const __nv_bfloat16* src = tsrc[t];
            const int rb = (t < 2) ? bm : bn;
#pragma unroll
            for (int i = 0; i < 2; i++) {
                int u = tid + i * 256;
                int row = u >> 2, seg = u & 3;
                const void* gp = src + (size_t)(rb + row) * K + k0 + seg * 8;
                uint32_t sp = db + (uint32_t)(t * TILE_B + row * 80 + seg * 16);
                cp_async16(sp, gp);
            }
        }
        CP_COMMIT();
    };

    const int nchunk = K / GK;
    load_chunk(0);

    for (int c = 0; c < nchunk; c++) {
        CP_WAIT0();
        __syncthreads();
        if (c + 1 < nchunk) load_chunk(c + 1);

        const uint32_t bb = sbase + (uint32_t)(c & 1) * BUF_B;
#pragma unroll
        for (int kc = 0; kc < 2; kc++) {
            const uint32_t kcoff = (uint32_t)(kc * 32 + acolb);
            uint32_t ahi_[2][4], alo_[2][4];
            ldm4(ahi_[0], bb + (uint32_t)((mrow0 + arow) * 80) + kcoff);
            ldm4(ahi_[1], bb + (uint32_t)((mrow0 + 16 + arow) * 80) + kcoff);
            ldm4(alo_[0], bb + TILE_B + (uint32_t)((mrow0 + arow) * 80) + kcoff);
            ldm4(alo_[1],
                 bb + TILE_B + (uint32_t)((mrow0 + 16 + arow) * 80) + kcoff);

#pragma unroll
            for (int nio = 0; nio < 2; nio++) {
                uint32_t bh[2][4], bl[2][4];
#pragma unroll
                for (int j = 0; j < 2; j++) {
                    const uint32_t boff =
                        (uint32_t)((ncol0 + (nio * 2 + j) * 16 + arow) * 80) +
                        kcoff;
                    ldm4(bh[j], bb + 2 * TILE_B + boff);
                    ldm4(bl[j], bb + 3 * TILE_B + boff);
                }
                const int n0 = nio * 4;
#pragma unroll
                for (int j = 0; j < 2; j++) {
                    mma_bf16(acc[0][n0 + 2 * j], ahi_[0], bh[j][0], bh[j][2]);
                    mma_bf16(acc[1][n0 + 2 * j], ahi_[1], bh[j][0], bh[j][2]);
                    mma_bf16(acc[0][n0 + 2 * j + 1], ahi_[0], bh[j][1], bh[j][3]);
                    mma_bf16(acc[1][n0 + 2 * j + 1], ahi_[1], bh[j][1], bh[j][3]);
                }
#pragma unroll
                for (int j = 0; j < 2; j++) {
                    mma_bf16(acc[0][n0 + 2 * j], ahi_[0], bl[j][0], bl[j][2]);
                    mma_bf16(acc[1][n0 + 2 * j], ahi_[1], bl[j][0], bl[j][2]);
                    mma_bf16(acc[0][n0 + 2 * j + 1], ahi_[0], bl[j][1], bl[j][3]);
                    mma_bf16(acc[1][n0 + 2 * j + 1], ahi_[1], bl[j][1], bl[j][3]);
                }
#pragma unroll
                for (int j = 0; j < 2; j++) {
                    mma_bf16(acc[0][n0 + 2 * j], alo_[0], bh[j][0], bh[j][2]);
                    mma_bf16(acc[1][n0 + 2 * j], alo_[1], bh[j][0], bh[j][2]);
                    mma_bf16(acc[0][n0 + 2 * j + 1], alo_[0], bh[j][1], bh[j][3]);
                    mma_bf16(acc[1][n0 + 2 * j + 1], alo_[1], bh[j][1], bh[j][3]);
                }
            }
        }
    }

#pragma unroll
    for (int mi = 0; mi < 2; mi++) {
        const int r0 = bm + mrow0 + mi * 16 + g;
#pragma unroll
        for (int ni = 0; ni < 8; ni++) {
            const int col = bn + ncol0 + ni * 8 + 2 * t4;
            float b0v = 0.f, b1v = 0.f;
            if (HAS_BIAS) { b0v = bias[col]; b1v = bias[col + 1]; }
            float vals[4];
            vals[0] = acc[mi][ni][0] + b0v; vals[1] = acc[mi][ni][1] + b1v;
            vals[2] = acc[mi][ni][2] + b0v; vals[3] = acc[mi][ni][3] + b1v;
            if (ROUND_TF32) {
#pragma unroll
                for (int q = 0; q < 4; q++)
                    vals[q] = __uint_as_float(f2tf32(vals[q]));
            }
            float2 v0, v1;
            v0.x = vals[0]; v0.y = vals[1];
            v1.x = vals[2]; v1.y = vals[3];
            *(float2*)(C + (size_t)r0 * N + col) = v0;
            *(float2*)(C + (size_t)(r0 + 8) * N + col) = v1;
        }
    }
}

// ---------------------------------------------------------------------------
// Fused shuffled-Q flash attention (tf32 mma.sync), v3.
// 256 threads (8 warps), 128 q-rows/block, KV tiles of 64, dbl-buffer.
// K columns (d) arrive pre-interleaved from g_qkv; Q staged interleaved.
// -> S-loop b0/b1 and Q-fragment loads are single LDS.64 (strides 72,
//    conflict-free per 16-lane phase).
// ---------------------------------------------------------------------------
#define KSTR 72
#define VSTR 72
#define QSTR 72
#define KVBUF 9216                    // words: 64*72 + 64*72
#define VOFF 4608                     // words: 64*72
#define ATT_SMEM (2 * KVBUF * 4)      // 73728 bytes

__global__ void __launch_bounds__(256, 2) attn_kernel(
    const float* __restrict__ qkv, const int* __restrict__ perms,
    __nv_bfloat16* __restrict__ out_hi, __nv_bfloat16* __restrict__ out_lo) {
    extern __shared__ uint32_t sms[];
    const uint32_t sbase = smem_u32(sms);

    const int bh = blockIdx.y;
    const int b = bh / HEADS;
    const int h = bh % HEADS;
    const int q0 = blockIdx.x * 128;

    const int tid = threadIdx.x;
    const int w = tid >> 5, l = tid & 31;
    const int g = l >> 2, t4 = l & 3;
    const int qr0 = w * 16;

    const float* qkv_b = qkv + (size_t)b * SEQ * QKV_COLS;
    const int hoff = h * DHEAD;

    const int cp_row = tid >> 4;
    const int cp_seg = (tid & 15) * 4;

    auto issue_kv = [&](int t, int bsel) {
        const int kv0 = t * 64;
        const float* kb = qkv_b + (size_t)kv0 * QKV_COLS + hoff + INNER + cp_seg;
        const float* vb = kb + INNER;
        const uint32_t kd = sbase + (uint32_t)(bsel * KVBUF) * 4;
#pragma unroll
        for (int i = 0; i < 4; i++) {
            const int row = cp_row + i * 16;
            cp_async16(kd + (uint32_t)(row * KSTR + cp_seg) * 4,
                       kb + (size_t)row * QKV_COLS);
        }
#pragma unroll
        for (int i = 0; i < 4; i++) {
            const int row = cp_row + i * 16;
            cp_async16(kd + (uint32_t)(VOFF + row * VSTR + cp_seg) * 4,
                       vb + (size_t)row * QKV_COLS);
        }
        CP_COMMIT();
    };

    issue_kv(0, 0);

    // Stage Q (permuted gather, scaled, tf32) into buffer 1, d-interleaved.
    const int* ph = perms + (size_t)h * (SEQ * DHEAD) + q0 * DHEAD;
#pragma unroll 4
    for (int it = 0; it < 32; it++) {
        int f = it * 256 + tid;
        int p = ph[f];
        int nn = p >> 6, dd = p & 63;
        int i = f >> 6, j = f & 63;
        sms[KVBUF + i * QSTR + dplace(j)] =
            f2tf32(qkv_b[(size_t)nn * QKV_COLS + hoff + dd] * 0.125f);
    }
    __syncthreads();

    uint32_t qf[8][4];
#pragma unroll
    for (int kc = 0; kc < 8; kc++) {
        uint2 u0 = *(const uint2*)&sms[KVBUF + (qr0 + g) * QSTR + kc * 8 + 2 * t4];
        uint2 u1 =
            *(const uint2*)&sms[KVBUF + (qr0 + g + 8) * QSTR + kc * 8 + 2 * t4];
        qf[kc][0] = u0.x; qf[kc][2] = u0.y;
        qf[kc][1] = u1.x; qf[kc][3] = u1.y;
    }
    __syncthreads();   // buf1 free for tile 1

    float m0 = -1e30f, m1 = -1e30f, l0 = 0.f, l1 = 0.f;
    float O[8][4];
#pragma unroll
    for (int dt = 0; dt < 8; dt++)
#pragma unroll
        for (int q = 0; q < 4; q++) O[dt][q] = 0.f;

    const int srcA = (l & 28) | (t4 >> 1);
    const int srcB = srcA | 2;
    const bool lo_lane = (t4 & 1) != 0;

    for (int t = 0; t < 16; t++) {
        if (t < 15) {
            issue_kv(t + 1, (t + 1) & 1);
            CP_WAIT1();
        } else {
            CP_WAIT0();
        }
        __syncthreads();

        const uint32_t kw = (uint32_t)(t & 1) * KVBUF;
        const uint32_t vw = kw + VOFF;

        float S[8][4];
#pragma unroll
        for (int nt = 0; nt < 8; nt++)
#pragma unroll
            for (int q = 0; q < 4; q++) S[nt][q] = 0.f;
#pragma unroll
        for (int kc = 0; kc < 8; kc++) {
#pragma unroll
            for (int nt = 0; nt < 8; nt++) {
                uint2 kk = *(const uint2*)&sms[kw + (nt * 8 + g) * KSTR +
                                               kc * 8 + 2 * t4];
                mma_tf32(S[nt], qf[kc], kk.x, kk.y);
            }
        }

        float mx0 = -1e30f, mx1 = -1e30f;
#pragma unroll
        for (int nt = 0; nt < 8; nt++) {
            mx0 = fmaxf(mx0, fmaxf(S[nt][0], S[nt][1]));
            mx1 = fmaxf(mx1, fmaxf(S[nt][2], S[nt][3]));
        }
        mx0 = fmaxf(mx0, __shfl_xor_sync(0xffffffffu, mx0, 1));
        mx0 = fmaxf(mx0, __shfl_xor_sync(0xffffffffu, mx0, 2));
        mx1 = fmaxf(mx1, __shfl_xor_sync(0xffffffffu, mx1, 1));
        mx1 = fmaxf(mx1, __shfl_xor_sync(0xffffffffu, mx1, 2));

        const float mn0 = fmaxf(m0, mx0);
        const float mn1 = fmaxf(m1, mx1);
        const float al0 = __expf(m0 - mn0);
        const float al1 = __expf(m1 - mn1);
        float sum0 = 0.f, sum1 = 0.f;
#pragma unroll
        for (int nt = 0; nt < 8; nt++) {
            S[nt][0] = __expf(S[nt][0] - mn0);
            S[nt][1] = __expf(S[nt][1] - mn0);
            S[nt][2] = __expf(S[nt][2] - mn1);
            S[nt][3] = __expf(S[nt][3] - mn1);
            sum0 += S[nt][0] + S[nt][1];
            sum1 += S[nt][2] + S[nt][3];
        }
        sum0 += __shfl_xor_sync(0xffffffffu, sum0, 1);
        sum0 += __shfl_xor_sync(0xffffffffu, sum0, 2);
        sum1 += __shfl_xor_sync(0xffffffffu, sum1, 1);
        sum1 += __shfl_xor_sync(0xffffffffu, sum1, 2);
        l0 = l0 * al0 + sum0;
        l1 = l1 * al1 + sum1;
        m0 = mn0; m1 = mn1;
#pragma unroll
        for (int dt = 0; dt < 8; dt++) {
            O[dt][0] *= al0; O[dt][1] *= al0;
            O[dt][2] *= al1; O[dt][3] *= al1;
        }

#pragma unroll
        for (int kc = 0; kc < 8; kc++) {
            uint32_t p0 = f2tf32(S[kc][0]);
            uint32_t p1 = f2tf32(S[kc][1]);
            uint32_t p2 = f2tf32(S[kc][2]);
            uint32_t p3 = f2tf32(S[kc][3]);
            uint32_t v00 = __shfl_sync(0xffffffffu, p0, srcA);
            uint32_t v01 = __shfl_sync(0xffffffffu, p1, srcA);
            uint32_t v10 = __shfl_sync(0xffffffffu, p2, srcA);
            uint32_t v11 = __shfl_sync(0xffffffffu, p3, srcA);
            uint32_t w00 = __shfl_sync(0xffffffffu, p0, srcB);
            uint32_t w01 = __shfl_sync(0xffffffffu, p1, srcB);
            uint32_t w10 = __shfl_sync(0xffffffffu, p2, srcB);
            uint32_t w11 = __shfl_sync(0xffffffffu, p3, srcB);
            uint32_t a[4];
            a[0] = lo_lane ? v01 : v00;
            a[1] = lo_lane ? v11 : v10;
            a[2] = lo_lane ? w01 : w00;
            a[3] = lo_lane ? w11 : w10;
#pragma unroll
            for (int dt = 0; dt < 8; dt++) {
                uint32_t b0 = sms[vw + (kc * 8 + t4) * VSTR + dt * 8 + g];
                uint32_t b1 = sms[vw + (kc * 8 + t4 + 4) * VSTR + dt * 8 + g];
                mma_tf32(O[dt], a, b0, b1);
            }
        }
        __syncthreads();
    }

    // Epilogue: normalize and write bf16 hi/lo pairs.
    const float inv0 = 1.0f / l0;
    const float inv1 = 1.0f / l1;
    const size_t r0off = ((size_t)b * SEQ + q0 + qr0 + g) * NDIM + hoff;
    const size_t r1off = r0off + (size_t)8 * NDIM;
#pragma unroll
    for (int dt = 0; dt < 8; dt++) {
        float f00 = O[dt][0] * inv0, f01 = O[dt][1] * inv0;
        float f10 = O[dt][2] * inv1, f11 = O[dt][3] * inv1;
        __nv_bfloat162 h0, h1, e0, e1;
        h0.x = __float2bfloat16(f00); h0.y = __float2bfloat16(f01);
        h1.x = __float2bfloat16(f10); h1.y = __float2bfloat16(f11);
        e0.x = __float2bfloat16(f00 - __bfloat162float(h0.x));
        e0.y = __float2bfloat16(f01 - __bfloat162float(h0.y));
        e1.x = __float2bfloat16(f10 - __bfloat162float(h1.x));
        e1.y = __float2bfloat16(f11 - __bfloat162float(h1.y));
        const int c = dt * 8 + 2 * t4;
        *(__nv_bfloat162*)(out_hi + r0off + c) = h0;
        *(__nv_bfloat162*)(out_lo + r0off + c) = e0;
        *(__nv_bfloat162*)(out_hi + r1off + c) = h1;
        *(__nv_bfloat162*)(out_lo + r1off + c) = e1;
    }
}

// ---------------------------------------------------------------------------
extern "C" void kernel_launch(void* const* d_in, const int* in_sizes, int n_in,
                              void* d_out, int out_size) {
    const float* x     = (const float*)d_in[0];
    const float* w_qkv = (const float*)d_in[1];
    const float* w_out = (const float*)d_in[2];
    const float* b_out = (const float*)d_in[3];
    const int*   perms = (const int*)d_in[4];
    float* out = (float*)d_out;

    float* qkv = nullptr;
    cudaGetSymbolAddress((void**)&qkv, g_qkv);
    __nv_bfloat16 *xhi, *xlo, *whi, *wlo, *ahi, *alo, *vhi, *vlo;
    cudaGetSymbolAddress((void**)&xhi, g_xhi);
    cudaGetSymbolAddress((void**)&xlo, g_xlo);
    cudaGetSymbolAddress((void**)&whi, g_whi);
    cudaGetSymbolAddress((void**)&wlo, g_wlo);
    cudaGetSymbolAddress((void**)&ahi, g_ahi);
    cudaGetSymbolAddress((void**)&alo, g_alo);
    cudaGetSymbolAddress((void**)&vhi, g_vhi);
    cudaGetSymbolAddress((void**)&vlo, g_vlo);

    cudaFuncSetAttribute(attn_kernel, cudaFuncAttributeMaxDynamicSharedMemorySize,
                         ATT_SMEM);
    cudaFuncSetAttribute((const void*)gemm_bf16x3<false, true>,
                         cudaFuncAttributeMaxDynamicSharedMemorySize, GEMM_SMEM);
    cudaFuncSetAttribute((const void*)gemm_bf16x3<true, false>,
                         cudaFuncAttributeMaxDynamicSharedMemorySize, GEMM_SMEM);

    // 1) split x / w_qkv (K-section d-interleaved) / w_out into bf16 hi/lo
    {
        int n4 = ROWS_TOTAL * NDIM / 4;
        cvt_hilo<<<2048, 256>>>(x, xhi, xlo, n4);
        int m4 = QKV_COLS * NDIM / 4;
        cvt_hilo_wqkv<<<1024, 256>>>(w_qkv, whi, wlo, m4);
        int v4 = NDIM * NDIM / 4;
        cvt_hilo<<<576, 256>>>(w_out, vhi, vlo, v4);
    }
    // 2) qkv = x @ w_qkv^T  (bf16x3 mma.sync, epilogue rounds to tf32)
    {
        dim3 grid(QKV_COLS / 128, ROWS_TOTAL / 128);  // (18, 64)
        gemm_bf16x3<false, true><<<grid, 256, GEMM_SMEM>>>(
            xhi, xlo, whi, wlo, nullptr, qkv, ROWS_TOTAL, QKV_COLS, NDIM);
    }
    // 3) fused shuffled-Q attention (tf32 mma.sync) -> bf16 hi/lo
    {
        dim3 grid(SEQ / 128, BATCH * HEADS);  // (8, 96)
        attn_kernel<<<grid, 256, ATT_SMEM>>>(qkv, perms, ahi, alo);
    }
    // 4) out = att @ w_out^T + b_out  (bf16x3 mma.sync)
    {
        dim3 grid(NDIM / 128, ROWS_TOTAL / 128);  // (6, 64)
        gemm_bf16x3<true, false><<<grid, 256, GEMM_SMEM>>>(
            ahi, alo, vhi, vlo, b_out, out, ROWS_TOTAL, NDIM, NDIM);
    }
}

// round 9
// speedup vs baseline: 1.2745x; 1.1814x over previous
#include <cuda_runtime.h>
#include <cuda_bf16.h>
#include <cstdint>
#include <math.h>

#define BATCH 8
#define SEQ 1024
#define NDIM 768
#define HEADS 12
#define DHEAD 64
#define INNER 768
#define QKV_COLS 2304
#define ROWS_TOTAL (BATCH * SEQ)   // 8192

// ---------------------------------------------------------------------------
// Device scratch (no cudaMalloc allowed)
// ---------------------------------------------------------------------------
__device__ float g_qkv[ROWS_TOTAL * QKV_COLS];   // fp32 (tf32-rounded)
__device__ float g_xt[ROWS_TOTAL * NDIM];        // x, tf32-rounded, cols interleaved
__device__ float g_wt[QKV_COLS * NDIM];          // w_qkv, rounded, col-ilv + K-row-ilv
__device__ float g_att[ROWS_TOTAL * NDIM];       // attention out, rounded, col-ilv
__device__ float g_wot[NDIM * NDIM];             // w_out, rounded, col-ilv

// ---------------------------------------------------------------------------
// Helpers (baseline PTX, valid on compute_103)
// ---------------------------------------------------------------------------
__device__ __forceinline__ uint32_t smem_u32(const void* p) {
    uint32_t a;
    asm("{ .reg .u64 t; cvta.to.shared.u64 t, %1; cvt.u32.u64 %0, t; }"
        : "=r"(a) : "l"(p));
    return a;
}

__device__ __forceinline__ uint32_t f2tf32(float f) {
    uint32_t u;
    asm("cvt.rna.tf32.f32 %0, %1;" : "=r"(u) : "f"(f));
    return u;
}
__device__ __forceinline__ float rtf(float f) {
    return __uint_as_float(f2tf32(f));
}

__device__ __forceinline__ void mma_tf32(float* c, const uint32_t* a,
                                         uint32_t b0, uint32_t b1) {
    asm volatile(
        "mma.sync.aligned.m16n8k8.row.col.f32.tf32.tf32.f32 "
        "{%0,%1,%2,%3},{%4,%5,%6,%7},{%8,%9},{%0,%1,%2,%3};"
        : "+f"(c[0]), "+f"(c[1]), "+f"(c[2]), "+f"(c[3])
        : "r"(a[0]), "r"(a[1]), "r"(a[2]), "r"(a[3]), "r"(b0), "r"(b1));
}

__device__ __forceinline__ void cp_async16(uint32_t dst, const void* src) {
    asm volatile("cp.async.cg.shared.global [%0], [%1], 16;" ::"r"(dst),
                 "l"(src));
}
#define CP_COMMIT() asm volatile("cp.async.commit_group;" ::: "memory")
#define CP_WAIT0() asm volatile("cp.async.wait_group 0;" ::: "memory")
#define CP_WAIT1() asm volatile("cp.async.wait_group 1;" ::: "memory")

// d-interleave placement: logical j within an 8-group -> storage position so
// that logical pairs (t4, t4+4) sit in adjacent words (LDS.64-able).
__device__ __forceinline__ int dplace(int j) {
    int b = j & 7;
    return (j & ~7) | (((b & 3) << 1) | (b >> 2));
}

// ---------------------------------------------------------------------------
// Conversion kernels: fp32 -> tf32-rounded fp32, k-columns interleaved.
// One 8-col group per thread iteration: out[0,1]=(b0,b4) out[2,3]=(b1,b5) ...
// ---------------------------------------------------------------------------
__global__ void __launch_bounds__(256) cvt_tf32(const float* __restrict__ src,
                                                float* __restrict__ dst,
                                                int ngroups) {
    int i = blockIdx.x * blockDim.x + threadIdx.x;
    int stride = gridDim.x * blockDim.x;
    for (; i < ngroups; i += stride) {
        float4 a = ((const float4*)src)[2 * i];
        float4 b = ((const float4*)src)[2 * i + 1];
        float2* d = (float2*)(dst + (size_t)i * 8);
        d[0] = make_float2(rtf(a.x), rtf(b.x));
        d[1] = make_float2(rtf(a.y), rtf(b.y));
        d[2] = make_float2(rtf(a.z), rtf(b.z));
        d[3] = make_float2(rtf(a.w), rtf(b.w));
    }
}

// w_qkv variant: additionally d-interleaves the ROWS of the K section
// [768,1536) so gemm1's K-output columns arrive pre-interleaved for the
// attention kernel's LDS.64 fragment loads.
__global__ void __launch_bounds__(256) cvt_tf32_wqkv(
    const float* __restrict__ src, float* __restrict__ dst, int ngroups) {
    const int GPR = NDIM / 8;  // 96 groups per row
    int i = blockIdx.x * blockDim.x + threadIdx.x;
    int stride = gridDim.x * blockDim.x;
    for (; i < ngroups; i += stride) {
        int row = i / GPR;
        int gc = i - row * GPR;
        int drow = row;
        if (row >= INNER && row < 2 * INNER) {
            int d = (row - INNER) & 63;
            drow = (row & ~63) | dplace(d);
        }
        float4 a = ((const float4*)src)[2 * i];
        float4 b = ((const float4*)src)[2 * i + 1];
        float2* d = (float2*)(dst + (size_t)drow * NDIM + gc * 8);
        d[0] = make_float2(rtf(a.x), rtf(b.x));
        d[1] = make_float2(rtf(a.y), rtf(b.y));
        d[2] = make_float2(rtf(a.z), rtf(b.z));
        d[3] = make_float2(rtf(a.w), rtf(b.w));
    }
}

// ---------------------------------------------------------------------------
// tf32 single-pass GEMM via mma.sync (NT): C = A @ B^T (+bias)
// A, B: fp32 tf32-rounded, k-columns interleaved (pairs (t4,t4+4) adjacent).
// 128x128 tile, BK=32 floats, 256 threads (8 warps, 32x64 each), dbl-buffer.
// smem row stride 40 words (160B; ==8 mod 32 -> conflict-free LDS.64).
// ---------------------------------------------------------------------------
#define FSTR 40
#define FTILE (128 * FSTR)        // words per operand tile (5120)
#define FBUF (2 * FTILE)          // A + B per buffer
#define TGEMM_SMEM (2 * FBUF * 4) // 81920 bytes

template <bool HAS_BIAS, bool ROUND_TF32>
__global__ void __launch_bounds__(256) gemm_tf32(
    const float* __restrict__ A, const float* __restrict__ B,
    const float* __restrict__ bias, float* __restrict__ C, int M, int N,
    int K) {
    extern __shared__ uint32_t sm4[];
    const uint32_t sbase = smem_u32(sm4);

    const int tid = threadIdx.x;
    const int w = tid >> 5, l = tid & 31;
    const int g = l >> 2, t4 = l & 3;
    const int bm = blockIdx.y * 128, bn = blockIdx.x * 128;
    const int mrow0 = (w & 3) * 32, ncol0 = (w >> 2) * 64;

    float acc[2][8][4];
#pragma unroll
    for (int mi = 0; mi < 2; mi++)
#pragma unroll
        for (int ni = 0; ni < 8; ni++)
#pragma unroll
            for (int q = 0; q < 4; q++) acc[mi][ni][q] = 0.f;

    auto load_chunk = [&](int c) {
        const int k0 = c * 32;
        const uint32_t db = sbase + (uint32_t)(c & 1) * (FBUF * 4);
#pragma unroll
        for (int op = 0; op < 2; op++) {
            const float* src = op ? B : A;
            const int rb = op ? bn : bm;
#pragma unroll
            for (int i = 0; i < 4; i++) {
                int u = tid + i * 256;           // 0..1023
                int row = u >> 3, seg = u & 7;   // 8 x 16B per row
                cp_async16(db + (uint32_t)(op * FTILE + row * FSTR + seg * 4) * 4,
                           src + (size_t)(rb + row) * K + k0 + seg * 4);
            }
        }
        CP_COMMIT();
    };

    const int nchunk = K / 32;
    load_chunk(0);

    for (int c = 0; c < nchunk; c++) {
        CP_WAIT0();
        __syncthreads();
        if (c + 1 < nchunk) load_chunk(c + 1);

        const uint32_t ab = (uint32_t)(c & 1) * FBUF;
        const uint32_t bbw = ab + FTILE;
#pragma unroll
        for (int k8 = 0; k8 < 4; k8++) {
            const int koff = k8 * 8 + 2 * t4;
            uint32_t af[2][4];
#pragma unroll
            for (int mi = 0; mi < 2; mi++) {
                const int r0 = mrow0 + mi * 16 + g;
                uint2 u0 = *(const uint2*)&sm4[ab + r0 * FSTR + koff];
                uint2 u1 = *(const uint2*)&sm4[ab + (r0 + 8) * FSTR + koff];
                af[mi][0] = u0.x; af[mi][1] = u1.x;
                af[mi][2] = u0.y; af[mi][3] = u1.y;
            }
#pragma unroll
            for (int nt = 0; nt < 8; nt++) {
                uint2 bb =
                    *(const uint2*)&sm4[bbw + (ncol0 + nt * 8 + g) * FSTR + koff];
                mma_tf32(acc[0][nt], af[0], bb.x, bb.y);
                mma_tf32(acc[1][nt], af[1], bb.x, bb.y);
            }
        }
    }

#pragma unroll
    for (int mi = 0; mi < 2; mi++) {
        const int r0 = bm + mrow0 + mi * 16 + g;
#pragma unroll
        for (int ni = 0; ni < 8; ni++) {
            const int col = bn + ncol0 + ni * 8 + 2 * t4;
            float b0v = 0.f, b1v = 0.f;
            if (HAS_BIAS) { b0v = bias[col]; b1v = bias[col + 1]; }
            float vals[4];
            vals[0] = acc[mi][ni][0] + b0v; vals[1] = acc[mi][ni][1] + b1v;
            vals[2] = acc[mi][ni][2] + b0v; vals[3] = acc[mi][ni][3] + b1v;
            if (ROUND_TF32) {
#pragma unroll
                for (int q = 0; q < 4; q++) vals[q] = rtf(vals[q]);
            }
            float2 v0, v1;
            v0.x = vals[0]; v0.y = vals[1];
            v1.x = vals[2]; v1.y = vals[3];
            *(float2*)(C + (size_t)r0 * N + col) = v0;
            *(float2*)(C + (size_t)(r0 + 8) * N + col) = v1;
        }
    }
}

// ---------------------------------------------------------------------------
// Fused shuffled-Q flash attention (tf32 mma.sync), v3 (R8 structure).
// 256 threads (8 warps), 128 q-rows/block, KV tiles of 64, dbl-buffer.
// K columns (d) arrive pre-interleaved from g_qkv; Q staged interleaved.
// Epilogue writes a single tf32-rounded fp32 att with interleaved columns.
// ---------------------------------------------------------------------------
#define KSTR 72
#define VSTR 72
#define QSTR 72
#define KVBUF 9216                    // words: 64*72 + 64*72
#define VOFF 4608                     // words: 64*72
#define ATT_SMEM (2 * KVBUF * 4)      // 73728 bytes

__global__ void __launch_bounds__(256, 2) attn_kernel(
    const float* __restrict__ qkv, const int* __restrict__ perms,
    float* __restrict__ att_out) {
    extern __shared__ uint32_t sms[];
    const uint32_t sbase = smem_u32(sms);

    const int bh = blockIdx.y;
    const int b = bh / HEADS;
    const int h = bh % HEADS;
    const int q0 = blockIdx.x * 128;

    const int tid = threadIdx.x;
    const int w = tid >> 5, l = tid & 31;
    const int g = l >> 2, t4 = l & 3;
    const int qr0 = w * 16;

    const float* qkv_b = qkv + (size_t)b * SEQ * QKV_COLS;
    const int hoff = h * DHEAD;

    const int cp_row = tid >> 4;
    const int cp_seg = (tid & 15) * 4;

    auto issue_kv = [&](int t, int bsel) {
        const int kv0 = t * 64;
        const float* kb = qkv_b + (size_t)kv0 * QKV_COLS + hoff + INNER + cp_seg;
        const float* vb = kb + INNER;
        const uint32_t kd = sbase + (uint32_t)(bsel * KVBUF) * 4;
#pragma unroll
        for (int i = 0; i < 4; i++) {
            const int row = cp_row + i * 16;
            cp_async16(kd + (uint32_t)(row * KSTR + cp_seg) * 4,
                       kb + (size_t)row * QKV_COLS);
        }
#pragma unroll
        for (int i = 0; i < 4; i++) {
            const int row = cp_row + i * 16;
            cp_async16(kd + (uint32_t)(VOFF + row * VSTR + cp_seg) * 4,
                       vb + (size_t)row * QKV_COLS);
        }
        CP_COMMIT();
    };

    issue_kv(0, 0);

    // Stage Q (permuted gather, scaled, tf32) into buffer 1, d-interleaved.
    const int* ph = perms + (size_t)h * (SEQ * DHEAD) + q0 * DHEAD;
#pragma unroll 4
    for (int it = 0; it < 32; it++) {
        int f = it * 256 + tid;
        int p = ph[f];
        int nn = p >> 6, dd = p & 63;
        int i = f >> 6, j = f & 63;
        sms[KVBUF + i * QSTR + dplace(j)] =
            f2tf32(qkv_b[(size_t)nn * QKV_COLS + hoff + dd] * 0.125f);
    }
    __syncthreads();

    uint32_t qf[8][4];
#pragma unroll
    for (int kc = 0; kc < 8; kc++) {
        uint2 u0 = *(const uint2*)&sms[KVBUF + (qr0 + g) * QSTR + kc * 8 + 2 * t4];
        uint2 u1 =
            *(const uint2*)&sms[KVBUF + (qr0 + g + 8) * QSTR + kc * 8 + 2 * t4];
        qf[kc][0] = u0.x; qf[kc][2] = u0.y;
        qf[kc][1] = u1.x; qf[kc][3] = u1.y;
    }
    __syncthreads();   // buf1 free for tile 1

    float m0 = -1e30f, m1 = -1e30f, l0 = 0.f, l1 = 0.f;
    float O[8][4];
#pragma unroll
    for (int dt = 0; dt < 8; dt++)
#pragma unroll
        for (int q = 0; q < 4; q++) O[dt][q] = 0.f;

    const int srcA = (l & 28) | (t4 >> 1);
    const int srcB = srcA | 2;
    const bool lo_lane = (t4 & 1) != 0;

    for (int t = 0; t < 16; t++) {
        if (t < 15) {
            issue_kv(t + 1, (t + 1) & 1);
            CP_WAIT1();
        } else {
            CP_WAIT0();
        }
        __syncthreads();

        const uint32_t kw = (uint32_t)(t & 1) * KVBUF;
        const uint32_t vw = kw + VOFF;

        float S[8][4];
#pragma unroll
        for (int nt = 0; nt < 8; nt++)
#pragma unroll
            for (int q = 0; q < 4; q++) S[nt][q] = 0.f;
#pragma unroll
        for (int kc = 0; kc < 8; kc++) {
#pragma unroll
            for (int nt = 0; nt < 8; nt++) {
                uint2 kk = *(const uint2*)&sms[kw + (nt * 8 + g) * KSTR +
                                               kc * 8 + 2 * t4];
                mma_tf32(S[nt], qf[kc], kk.x, kk.y);
            }
        }

        float mx0 = -1e30f, mx1 = -1e30f;
#pragma unroll
        for (int nt = 0; nt < 8; nt++) {
            mx0 = fmaxf(mx0, fmaxf(S[nt][0], S[nt][1]));
            mx1 = fmaxf(mx1, fmaxf(S[nt][2], S[nt][3]));
        }
        mx0 = fmaxf(mx0, __shfl_xor_sync(0xffffffffu, mx0, 1));
        mx0 = fmaxf(mx0, __shfl_xor_sync(0xffffffffu, mx0, 2));
        mx1 = fmaxf(mx1, __shfl_xor_sync(0xffffffffu, mx1, 1));
        mx1 = fmaxf(mx1, __shfl_xor_sync(0xffffffffu, mx1, 2));

        const float mn0 = fmaxf(m0, mx0);
        const float mn1 = fmaxf(m1, mx1);
        const float al0 = __expf(m0 - mn0);
        const float al1 = __expf(m1 - mn1);
        float sum0 = 0.f, sum1 = 0.f;
#pragma unroll
        for (int nt = 0; nt < 8; nt++) {
            S[nt][0] = __expf(S[nt][0] - mn0);
            S[nt][1] = __expf(S[nt][1] - mn0);
            S[nt][2] = __expf(S[nt][2] - mn1);
            S[nt][3] = __expf(S[nt][3] - mn1);
            sum0 += S[nt][0] + S[nt][1];
            sum1 += S[nt][2] + S[nt][3];
        }
        sum0 += __shfl_xor_sync(0xffffffffu, sum0, 1);
        sum0 += __shfl_xor_sync(0xffffffffu, sum0, 2);
        sum1 += __shfl_xor_sync(0xffffffffu, sum1, 1);
        sum1 += __shfl_xor_sync(0xffffffffu, sum1, 2);
        l0 = l0 * al0 + sum0;
        l1 = l1 * al1 + sum1;
        m0 = mn0; m1 = mn1;
#pragma unroll
        for (int dt = 0; dt < 8; dt++) {
            O[dt][0] *= al0; O[dt][1] *= al0;
            O[dt][2] *= al1; O[dt][3] *= al1;
        }

#pragma unroll
        for (int kc = 0; kc < 8; kc++) {
            uint32_t p0 = f2tf32(S[kc][0]);
            uint32_t p1 = f2tf32(S[kc][1]);
            uint32_t p2 = f2tf32(S[kc][2]);
            uint32_t p3 = f2tf32(S[kc][3]);
            uint32_t v00 = __shfl_sync(0xffffffffu, p0, srcA);
            uint32_t v01 = __shfl_sync(0xffffffffu, p1, srcA);
            uint32_t v10 = __shfl_sync(0xffffffffu, p2, srcA);
            uint32_t v11 = __shfl_sync(0xffffffffu, p3, srcA);
            uint32_t w00 = __shfl_sync(0xffffffffu, p0, srcB);
            uint32_t w01 = __shfl_sync(0xffffffffu, p1, srcB);
            uint32_t w10 = __shfl_sync(0xffffffffu, p2, srcB);
            uint32_t w11 = __shfl_sync(0xffffffffu, p3, srcB);
            uint32_t a[4];
            a[0] = lo_lane ? v01 : v00;
            a[1] = lo_lane ? v11 : v10;
            a[2] = lo_lane ? w01 : w00;
            a[3] = lo_lane ? w11 : w10;
#pragma unroll
            for (int dt = 0; dt < 8; dt++) {
                uint32_t b0 = sms[vw + (kc * 8 + t4) * VSTR + dt * 8 + g];
                uint32_t b1 = sms[vw + (kc * 8 + t4 + 4) * VSTR + dt * 8 + g];
                mma_tf32(O[dt], a, b0, b1);
            }
        }
        __syncthreads();
    }

    // Epilogue: normalize, tf32-round, write fp32 att with interleaved cols.
    const float inv0 = 1.0f / l0;
    const float inv1 = 1.0f / l1;
    const size_t r0off = ((size_t)b * SEQ + q0 + qr0 + g) * NDIM + hoff;
    const size_t r1off = r0off + (size_t)8 * NDIM;
    const int p0c = dplace(2 * t4);
    const int p1c = dplace(2 * t4 + 1);
#pragma unroll
    for (int dt = 0; dt < 8; dt++) {
        att_out[r0off + dt * 8 + p0c] = rtf(O[dt][0] * inv0);
        att_out[r0off + dt * 8 + p1c] = rtf(O[dt][1] * inv0);
        att_out[r1off + dt * 8 + p0c] = rtf(O[dt][2] * inv1);
        att_out[r1off + dt * 8 + p1c] = rtf(O[dt][3] * inv1);
    }
}

// ---------------------------------------------------------------------------
extern "C" void kernel_launch(void* const* d_in, const int* in_sizes, int n_in,
                              void* d_out, int out_size) {
    const float* x     = (const float*)d_in[0];
    const float* w_qkv = (const float*)d_in[1];
    const float* w_out = (const float*)d_in[2];
    const float* b_out = (const float*)d_in[3];
    const int*   perms = (const int*)d_in[4];
    float* out = (float*)d_out;

    float *qkv, *xt, *wt, *att, *wot;
    cudaGetSymbolAddress((void**)&qkv, g_qkv);
    cudaGetSymbolAddress((void**)&xt, g_xt);
    cudaGetSymbolAddress((void**)&wt, g_wt);
    cudaGetSymbolAddress((void**)&att, g_att);
    cudaGetSymbolAddress((void**)&wot, g_wot);

    cudaFuncSetAttribute(attn_kernel, cudaFuncAttributeMaxDynamicSharedMemorySize,
                         ATT_SMEM);
    cudaFuncSetAttribute((const void*)gemm_tf32<false, true>,
                         cudaFuncAttributeMaxDynamicSharedMemorySize, TGEMM_SMEM);
    cudaFuncSetAttribute((const void*)gemm_tf32<true, false>,
                         cudaFuncAttributeMaxDynamicSharedMemorySize, TGEMM_SMEM);

    // 1) tf32-round + k-col interleave: x, w_qkv (also K-row ilv), w_out
    {
        cvt_tf32<<<1024, 256>>>(x, xt, ROWS_TOTAL * NDIM / 8);
        cvt_tf32_wqkv<<<512, 256>>>(w_qkv, wt, QKV_COLS * NDIM / 8);
        cvt_tf32<<<192, 256>>>(w_out, wot, NDIM * NDIM / 8);
    }
    // 2) qkv = x @ w_qkv^T  (tf32 mma.sync, epilogue rounds to tf32)
    {
        dim3 grid(QKV_COLS / 128, ROWS_TOTAL / 128);  // (18, 64)
        gemm_tf32<false, true><<<grid, 256, TGEMM_SMEM>>>(
            xt, wt, nullptr, qkv, ROWS_TOTAL, QKV_COLS, NDIM);
    }
    // 3) fused shuffled-Q attention (tf32 mma.sync) -> att (fp32, col-ilv)
    {
        dim3 grid(SEQ / 128, BATCH * HEADS);  // (8, 96)
        attn_kernel<<<grid, 256, ATT_SMEM>>>(qkv, perms, att);
    }
    // 4) out = att @ w_out^T + b_out  (tf32 mma.sync)
    {
        dim3 grid(NDIM / 128, ROWS_TOTAL / 128);  // (6, 64)
        gemm_tf32<true, false><<<grid, 256, TGEMM_SMEM>>>(
            att, wot, b_out, out, ROWS_TOTAL, NDIM, NDIM);
    }
}